// round 1
// baseline (speedup 1.0000x reference)
#include <cuda_runtime.h>
#include <math.h>

#define TMAX 256
#define LOG2PI 1.8378770664093453f

// Device scratch (allowed: static __device__ arrays, no allocation)
__device__ float g_P[TMAX][256];   // bA_t for t>=1
__device__ float g_ba[TMAX][16];   // ba_t for t>=1

struct SM {
    // constants
    float Wq[256], Sq[256], Hq[256], Rq[256];
    float Wp[256], Wep[256];
    float Om_p[256], om[256], Om0[256];
    float ctM[256], Cq[256], Fm[256], Em[256];
    // dynamic matrices
    float fc[256], fprec[256], bcov[256], bA[256];
    float G[256], Go[256];
    float t0[256], t1[256], t2[256], t3[256];
    float pc[256], S[256], K[256], Hpc[256];
    float A[256], Ao[256], Rm[256];
    // vectors
    float bq[16], dq[16], ctb[16], bp[16], ebp[16], ppm[16];
    float fm[16], ba[16], u[16], y[16];
    float vec0[16], vec1[16], vec2[16], vec3[16];
    // GJ work buffers (stride 48 floats for conflict-free access)
    float w0[16 * 48], w1[16 * 48];
    float red[8];
};

__device__ __forceinline__ float dot_rc(const float* A, const float* B, int i, int j) {
    float s = 0.f;
#pragma unroll
    for (int k = 0; k < 16; k++) s = fmaf(A[i * 16 + k], B[k * 16 + j], s);
    return s;
}
__device__ __forceinline__ float dot_tc(const float* A, const float* B, int i, int j) { // A^T B
    float s = 0.f;
#pragma unroll
    for (int k = 0; k < 16; k++) s = fmaf(A[k * 16 + i], B[k * 16 + j], s);
    return s;
}
__device__ __forceinline__ float dot_rt(const float* A, const float* B, int i, int j) { // A B^T
    float s = 0.f;
#pragma unroll
    for (int k = 0; k < 16; k++) s = fmaf(A[i * 16 + k], B[j * 16 + k], s);
    return s;
}
__device__ __forceinline__ float mv(const float* M, const float* v, int r) {
    float s = 0.f;
#pragma unroll
    for (int k = 0; k < 16; k++) s = fmaf(M[r * 16 + k], v[k], s);
    return s;
}

__device__ __forceinline__ float block_sum(float v, float* red, int tid) {
#pragma unroll
    for (int o = 16; o; o >>= 1) v += __shfl_xor_sync(0xffffffffu, v, o);
    if ((tid & 31) == 0) red[tid >> 5] = v;
    __syncthreads();
    if (tid < 32) {
        float x = (tid < 8) ? red[tid] : 0.f;
#pragma unroll
        for (int o = 4; o; o >>= 1) x += __shfl_xor_sync(0xffffffffu, x, o);
        if (tid == 0) red[0] = x;
    }
    __syncthreads();
    float r = red[0];
    __syncthreads();
    return r;
}

// Gauss-Jordan inverse of SPD 16x16 (no pivoting). Returns sum(log pivots)
// (= logdet(M)) on all threads when want_ld is true.
__device__ __forceinline__ float gj_inv(float* w0, float* w1, const float* M,
                                        float* OUT, int i, int j, bool want_ld) {
    w0[i * 48 + j] = M[i * 16 + j];
    w0[i * 48 + 16 + j] = (i == j) ? 1.f : 0.f;
    __syncthreads();
    float* cur = w0;
    float* nxt = w1;
    float ld = 0.f;
#pragma unroll 4
    for (int p = 0; p < 16; p++) {
        float piv = cur[p * 48 + p];
        float pivinv = 1.f / piv;
        if (want_ld) ld += __logf(piv);
        float rp0 = cur[p * 48 + j] * pivinv;
        float rp1 = cur[p * 48 + 16 + j] * pivinv;
        float n0, n1;
        if (i == p) {
            n0 = rp0;
            n1 = rp1;
        } else {
            float f = cur[i * 48 + p];
            n0 = cur[i * 48 + j] - f * rp0;
            n1 = cur[i * 48 + 16 + j] - f * rp1;
        }
        nxt[i * 48 + j] = n0;
        nxt[i * 48 + 16 + j] = n1;
        __syncthreads();
        float* tp = cur; cur = nxt; nxt = tp;
    }
    OUT[i * 16 + j] = cur[i * 48 + 16 + j];
    __syncthreads();
    return ld;
}

// Kalman update: pm in s.vec0, pc in s.pc, y in s.y -> writes s.fm, s.fc.
__device__ __forceinline__ void kalman(SM& s, int i, int j, int tid) {
    s.Hpc[tid] = dot_rc(s.Hq, s.pc, i, j);
    if (tid < 16) s.vec1[tid] = s.y[tid] - mv(s.Hq, s.vec0, tid) - s.dq[tid];
    __syncthreads();
    s.S[tid] = dot_rt(s.Hpc, s.Hq, i, j) + s.Rq[tid];
    __syncthreads();
    gj_inv(s.w0, s.w1, s.S, s.t0, i, j, false);  // t0 = S^-1
    s.K[tid] = dot_tc(s.Hpc, s.t0, i, j);        // K = pc H^T S^-1 (pc sym)
    __syncthreads();
    s.fc[tid] = s.pc[tid] - dot_rc(s.K, s.Hpc, i, j);
    if (tid < 16) s.fm[tid] = s.vec0[tid] + mv(s.K, s.vec1, tid);
    __syncthreads();
}

__global__ void __launch_bounds__(256, 1) lgq_kernel(
    const float* obs, const float* p_prior_mean, const float* p_prior_cov,
    const float* p_trans_w, const float* p_trans_b, const float* p_trans_cov,
    const float* p_emis_w, const float* p_emis_b, const float* p_emis_cov,
    const float* q_prior_mean, const float* q_prior_cov, const float* q_trans_w,
    const float* q_trans_b, const float* q_trans_cov, const float* q_emis_w,
    const float* q_emis_b, const float* q_emis_cov, float* out, int Tn) {
    __shared__ SM s;
    const int tid = threadIdx.x;
    const int i = tid >> 4, j = tid & 15;
    double acc = 0.0;  // identical on all threads

    // ---- load constants ----
    s.Wq[tid] = q_trans_w[tid];
    s.Sq[tid] = q_trans_cov[tid];
    s.Hq[tid] = q_emis_w[tid];
    s.Rq[tid] = q_emis_cov[tid];
    s.Wp[tid] = p_trans_w[tid];
    s.Wep[tid] = p_emis_w[tid];
    if (tid < 16) {
        s.bq[tid] = q_trans_b[tid];
        s.dq[tid] = q_emis_b[tid];
        s.bp[tid] = p_trans_b[tid];
        s.ebp[tid] = p_emis_b[tid];
        s.ppm[tid] = p_prior_mean[tid];
    }
    __syncthreads();

    // ---- precompute inverses / derived constants ----
    float LDp = gj_inv(s.w0, s.w1, p_trans_cov, s.t1, i, j, true);  // t1 = Pp
    s.Om_p[tid] = -0.5f * s.t1[tid];
    s.t2[tid] = dot_rc(s.t1, s.Wp, i, j);  // Pp @ Wp
    __syncthreads();
    s.Fm[tid] = dot_tc(s.Wp, s.t2, i, j);  // F = Wp^T Pp Wp

    float LDe = gj_inv(s.w0, s.w1, p_emis_cov, s.t1, i, j, true);  // t1 = Pe
    s.om[tid] = -0.5f * s.t1[tid];
    __syncthreads();
    s.t2[tid] = dot_rc(s.om, s.Wep, i, j);
    __syncthreads();
    s.Em[tid] = dot_tc(s.Wep, s.t2, i, j);  // E = Wep^T om Wep

    float LDpr = gj_inv(s.w0, s.w1, p_prior_cov, s.t1, i, j, true);
    s.Om0[tid] = -0.5f * s.t1[tid];

    gj_inv(s.w0, s.w1, q_trans_cov, s.t1, i, j, false);  // t1 = Lambda_q
    s.ctM[tid] = dot_tc(s.Wq, s.t1, i, j);               // ct = Wq^T Lq
    __syncthreads();
    s.Cq[tid] = dot_rc(s.ctM, s.Wq, i, j);  // ct @ Wq
    if (tid < 16) s.ctb[tid] = mv(s.ctM, s.bq, tid);
    s.G[tid] = s.Om0[tid];
    s.Go[tid] = s.Em[tid];
    s.pc[tid] = q_prior_cov[tid];
    if (tid < 16) {
        s.vec0[tid] = q_prior_mean[tid];
        s.y[tid] = obs[tid];
    }
    __syncthreads();

    // initial Kalman update (t = 0)
    kalman(s, i, j, tid);

    acc = -0.5 * (16.0 * (double)LOG2PI + (double)LDpr)
        - 0.5 * (16.0 * (double)LOG2PI + (double)LDe);
    const float K0 = -8.f * LOG2PI - 0.5f * LDe - 0.5f * LDp + 8.f;

    // ================= forward pass =================
    for (int t = 1; t < Tn; t++) {
        gj_inv(s.w0, s.w1, s.fc, s.fprec, i, j, false);  // fprec = fc^-1
        s.t0[tid] = s.Cq[tid] + s.fprec[tid];            // bprec
        __syncthreads();
        float ldb = gj_inv(s.w0, s.w1, s.t0, s.bcov, i, j, true);  // logdet(bprec)

        s.bA[tid] = dot_rc(s.bcov, s.ctM, i, j);
        if (tid < 16) {
            s.vec0[tid] = mv(s.fprec, s.fm, tid) - s.ctb[tid];
            s.y[tid] = obs[t * 16 + tid];
        }
        __syncthreads();
        if (tid < 16) s.ba[tid] = mv(s.bcov, s.vec0, tid);
        float val = (s.G[tid] + s.Go[tid] - 0.5f * s.Fm[tid]) * s.bcov[tid];
        float r = block_sum(val, s.red, tid);
        acc += (double)(K0 - 0.5f * ldb + r);
        g_P[t][tid] = s.bA[tid];
        if (tid < 16) g_ba[t][tid] = s.ba[tid];

        // region A: A_new, G@bA, Go@bA, Wq@fc, pm
        s.t1[tid] = dot_rc(s.Wp, s.bA, i, j) - ((i == j) ? 1.f : 0.f);
        s.t2[tid] = dot_rc(s.G, s.bA, i, j);
        s.t3[tid] = dot_rc(s.Go, s.bA, i, j);
        s.t0[tid] = dot_rc(s.Wq, s.fc, i, j);
        if (tid < 16) s.vec0[tid] = mv(s.Wq, s.fm, tid) + s.bq[tid];  // pm
        __syncthreads();
        // region B
        s.G[tid] = dot_tc(s.bA, s.t2, i, j);
        s.Go[tid] = dot_tc(s.bA, s.t3, i, j) + s.Em[tid];
        s.S[tid] = dot_rc(s.Om_p, s.t1, i, j);                // Om_p @ A_new
        s.pc[tid] = dot_rt(s.t0, s.Wq, i, j) + s.Sq[tid];     // pc
        __syncthreads();
        // region C: G += A_new^T (Om_p A_new)
        s.G[tid] += dot_tc(s.t1, s.S, i, j);
        __syncthreads();
        kalman(s, i, j, tid);
    }

    // final fc logdet
    float ldfc = gj_inv(s.w0, s.w1, s.fc, s.t0, i, j, true);
    acc += 0.5 * (16.0 * (double)LOG2PI + (double)ldfc) + 8.0;

    // ================= backward pass =================
    s.Rm[tid] = (i == j) ? 1.f : 0.f;
    if (tid < 16) s.u[tid] = 0.f;
    __syncthreads();

    for (int t = Tn - 1; t >= 0; t--) {
        if (t > 0) {
            s.bA[tid] = g_P[t][tid];
            if (tid < 16) s.vec0[tid] = g_ba[t][tid];
        }
        if (tid < 16) s.y[tid] = obs[t * 16 + tid];
        __syncthreads();
        // region 1: A_init, b_init, Ao = Wep@R, Wep@u
        if (t > 0)
            s.t1[tid] = dot_rc(s.Wp, s.bA, i, j) - ((i == j) ? 1.f : 0.f);
        else
            s.t1[tid] = (i == j) ? 1.f : 0.f;
        s.Ao[tid] = dot_rc(s.Wep, s.Rm, i, j);
        if (tid < 16) {
            s.vec1[tid] = (t > 0) ? (mv(s.Wp, s.vec0, tid) + s.bp[tid]) : (-s.ppm[tid]);
            s.vec2[tid] = mv(s.Wep, s.u, tid);
        }
        __syncthreads();
        // region 2: A = A_init@R, R' = P@R, Ao@fc, B, u', Bo
        s.A[tid] = dot_rc(s.t1, s.Rm, i, j);
        if (t > 0) s.t3[tid] = dot_rc(s.bA, s.Rm, i, j);
        s.t2[tid] = dot_rc(s.Ao, s.fc, i, j);
        if (tid < 16) {
            s.vec1[tid] += mv(s.t1, s.u, tid);                       // B_final
            if (t > 0) s.vec3[tid] = s.vec0[tid] + mv(s.bA, s.u, tid);  // u_t
            s.vec2[tid] = s.ebp[tid] - s.y[tid] + s.vec2[tid];       // Bo_final
        }
        __syncthreads();
        // region 3: A@fc, (Ao fc)@Ao, cv, co
        s.t0[tid] = dot_rc(s.A, s.fc, i, j);
        s.pc[tid] = dot_rc(s.t2, s.Ao, i, j);  // No2 = Ao fc Ao
        if (tid < 16) {
            s.vec0[tid] = mv(s.A, s.fm, tid) + s.vec1[tid];   // cv
            s.vec2[tid] = mv(s.Ao, s.fm, tid) + s.vec2[tid];  // co
        }
        __syncthreads();
        // region 4: N2 = (A fc) A
        s.S[tid] = dot_rc(s.t0, s.A, i, j);
        __syncthreads();
        const float* Om = (t == 0) ? s.Om0 : s.Om_p;
        float val = Om[tid] * (s.S[tid] + s.vec0[i] * s.vec0[j])
                  + s.om[tid] * (s.pc[tid] + s.vec2[i] * s.vec2[j]);
        float r = block_sum(val, s.red, tid);
        acc += (double)r;
        if (t > 0) {
            s.Rm[tid] = s.t3[tid];
            if (tid < 16) s.u[tid] = s.vec3[tid];
        }
        __syncthreads();
    }

    if (tid == 0) out[0] = (float)acc;
}

extern "C" void kernel_launch(void* const* d_in, const int* in_sizes, int n_in,
                              void* d_out, int out_size) {
    int Tn = in_sizes[0] / 16;
    if (Tn > TMAX) Tn = TMAX;
    lgq_kernel<<<1, 256>>>(
        (const float*)d_in[0], (const float*)d_in[1], (const float*)d_in[2],
        (const float*)d_in[3], (const float*)d_in[4], (const float*)d_in[5],
        (const float*)d_in[6], (const float*)d_in[7], (const float*)d_in[8],
        (const float*)d_in[9], (const float*)d_in[10], (const float*)d_in[11],
        (const float*)d_in[12], (const float*)d_in[13], (const float*)d_in[14],
        (const float*)d_in[15], (const float*)d_in[16], (float*)d_out, Tn);
}

// round 2
// speedup vs baseline: 1.9338x; 1.9338x over previous
#include <cuda_runtime.h>
#include <math.h>

#define TMAX 256
#define LOG2PI 1.8378770664093453

__device__ float g_P[TMAX][256];   // bA_t for t>=1
__device__ float g_ba[TMAX][16];   // ba_t for t>=1

struct SM {
    // constants
    float Wq[256], Sq[256], Hq[256], Rq[256], Wp[256], Wep[256];
    float Om_p[256], om[256], Om0[256], Em[256], Fm[256];
    // dynamics
    float fc[256], fcn[256], M[256], pc[256], Hpc[256], S[256];
    float bA[256], K[256], bcov[256], t1[256], t2[256], t3[256], OmpA[256];
    float G[256], Go[256];
    float A[256], Ao[256], Rm[256];
    // vectors
    float bq[16], dq[16], bp[16], ebp[16], ppm[16];
    float fm[16], fmn[16], pm[16], innov[16], y[16], u[16];
    float vec0[16], vec1[16], vec2[16], vec3[16];
    float ld_a, ld_b;
    double dred[8];
};

__device__ __forceinline__ float dot_rc(const float* A, const float* B, int i, int j) {
    float s = 0.f;
#pragma unroll
    for (int k = 0; k < 16; k++) s = fmaf(A[i * 16 + k], B[k * 16 + j], s);
    return s;
}
__device__ __forceinline__ float dot_tc(const float* A, const float* B, int i, int j) { // A^T B
    float s = 0.f;
#pragma unroll
    for (int k = 0; k < 16; k++) s = fmaf(A[k * 16 + i], B[k * 16 + j], s);
    return s;
}
__device__ __forceinline__ float dot_rowreg_col(const float* row, const float* B, int j) {
    float s = 0.f;
#pragma unroll
    for (int k = 0; k < 16; k++) s = fmaf(row[k], B[k * 16 + j], s);
    return s;
}
__device__ __forceinline__ float dot_row_rowreg(const float* A, const float* row, int i) {
    float s = 0.f;
#pragma unroll
    for (int k = 0; k < 16; k++) s = fmaf(A[i * 16 + k], row[k], s);
    return s;
}
__device__ __forceinline__ float mv(const float* M, const float* v, int r) {
    float s = 0.f;
#pragma unroll
    for (int k = 0; k < 16; k++) s = fmaf(M[r * 16 + k], v[k], s);
    return s;
}

// Single-warp register-resident Gauss-Jordan solve:  A (16x16 SPD) X = B.
// Lane l<16 owns column l of A; lane l>=16 owns column l-16 of B.
// Writes Xt = X^T (row-major 16x16) to smem. Returns logdet(A) on all lanes.
__device__ __forceinline__ float warp_gj_solve(const float* Am, const float* Bm,
                                               float* Xt, int lane) {
    float a[16];
    {
        const float* src = (lane < 16) ? (Am + lane) : (Bm + lane - 16);
#pragma unroll
        for (int r = 0; r < 16; r++) a[r] = src[r * 16];
    }
    float mypiv = 1.f;
#pragma unroll
    for (int p = 0; p < 16; p++) {
        float f[16];
#pragma unroll
        for (int r = 0; r < 16; r++) f[r] = __shfl_sync(0xffffffffu, a[r], p);
        float x = f[p];
        if (lane == p) mypiv = x;
        float r0;
        asm("rcp.approx.f32 %0, %1;" : "=f"(r0) : "f"(x));
        float pivinv = r0 * (2.0f - x * r0);  // one Newton step
        a[p] *= pivinv;
#pragma unroll
        for (int r = 0; r < 16; r++)
            if (r != p) a[r] = fmaf(-f[r], a[p], a[r]);
    }
    float lg = __logf(mypiv);  // lanes >=16 contribute log(1)=0
#pragma unroll
    for (int o = 16; o; o >>= 1) lg += __shfl_xor_sync(0xffffffffu, lg, o);
    if (lane >= 16) {
        float4* dst = reinterpret_cast<float4*>(Xt + (lane - 16) * 16);
        dst[0] = make_float4(a[0], a[1], a[2], a[3]);
        dst[1] = make_float4(a[4], a[5], a[6], a[7]);
        dst[2] = make_float4(a[8], a[9], a[10], a[11]);
        dst[3] = make_float4(a[12], a[13], a[14], a[15]);
    }
    return lg;
}

__global__ void __launch_bounds__(256, 1) lgq_kernel(
    const float* obs, const float* p_prior_mean, const float* p_prior_cov,
    const float* p_trans_w, const float* p_trans_b, const float* p_trans_cov,
    const float* p_emis_w, const float* p_emis_b, const float* p_emis_cov,
    const float* q_prior_mean, const float* q_prior_cov, const float* q_trans_w,
    const float* q_trans_b, const float* q_trans_cov, const float* q_emis_w,
    const float* q_emis_b, const float* q_emis_cov, float* out, int Tn) {
    __shared__ SM s;
    const int tid = threadIdx.x;
    const int i = tid >> 4, j = tid & 15;
    const int lane = tid & 31, wid = tid >> 5;

    // ---- load constants ----
    s.Wq[tid] = q_trans_w[tid];
    s.Sq[tid] = q_trans_cov[tid];
    s.Hq[tid] = q_emis_w[tid];
    s.Rq[tid] = q_emis_cov[tid];
    s.Wp[tid] = p_trans_w[tid];
    s.Wep[tid] = p_emis_w[tid];
    if (tid < 16) {
        s.bq[tid] = q_trans_b[tid];
        s.dq[tid] = q_emis_b[tid];
        s.bp[tid] = p_trans_b[tid];
        s.ebp[tid] = p_emis_b[tid];
        s.ppm[tid] = p_prior_mean[tid];
    }
    __syncthreads();

    // cached rows
    float wq_i[16], wq_j[16], hq_i[16], hq_j[16];
#pragma unroll
    for (int k = 0; k < 16; k++) {
        wq_i[k] = s.Wq[i * 16 + k];
        wq_j[k] = s.Wq[j * 16 + k];
        hq_i[k] = s.Hq[i * 16 + k];
        hq_j[k] = s.Hq[j * 16 + k];
    }

    // ---- setup: inverses / logdets (warp0 sequential GJ, setup cost trivial) ----
    float LDp = 0.f, LDe = 0.f, LDpr = 0.f, LDSq = 0.f, LDRq = 0.f, ldqp = 0.f, ldS0 = 0.f;
    s.t2[tid] = (i == j) ? 1.f : 0.f;  // identity, preserved (GJ never writes inputs)
    s.fc[tid] = p_trans_cov[tid];
    __syncthreads();
    if (wid == 0) LDp = warp_gj_solve(s.fc, s.t2, s.bcov, lane);
    __syncthreads();
    s.Om_p[tid] = -0.5f * s.bcov[tid];
    s.t3[tid] = dot_rc(s.bcov, s.Wp, i, j);  // Pp @ Wp
    __syncthreads();
    s.Fm[tid] = dot_tc(s.Wp, s.t3, i, j);
    s.fc[tid] = p_emis_cov[tid];
    __syncthreads();
    if (wid == 0) LDe = warp_gj_solve(s.fc, s.t2, s.bcov, lane);
    __syncthreads();
    s.om[tid] = -0.5f * s.bcov[tid];
    s.fc[tid] = p_prior_cov[tid];
    __syncthreads();
    s.t3[tid] = dot_rc(s.om, s.Wep, i, j);
    if (wid == 0) LDpr = warp_gj_solve(s.fc, s.t2, s.bcov, lane);
    __syncthreads();
    s.Em[tid] = dot_tc(s.Wep, s.t3, i, j);
    s.Om0[tid] = -0.5f * s.bcov[tid];
    s.fc[tid] = q_trans_cov[tid];
    __syncthreads();
    if (wid == 0) LDSq = warp_gj_solve(s.fc, s.t2, s.t3, lane);
    __syncthreads();
    s.fc[tid] = q_emis_cov[tid];
    __syncthreads();
    if (wid == 0) LDRq = warp_gj_solve(s.fc, s.t2, s.t3, lane);
    __syncthreads();

    // ---- initial Kalman update (t = 0), pc = q_prior_cov ----
    s.pc[tid] = q_prior_cov[tid];
    if (tid < 16) {
        s.pm[tid] = q_prior_mean[tid];
        s.y[tid] = obs[tid];
    }
    __syncthreads();
    if (wid == 0) ldqp = warp_gj_solve(s.pc, s.t2, s.t3, lane);
    __syncthreads();
    s.Hpc[tid] = dot_rowreg_col(hq_i, s.pc, j);
    if (tid < 16) s.innov[tid] = s.y[tid] - mv(s.Hq, s.pm, tid) - s.dq[tid];
    __syncthreads();
    s.S[tid] = dot_row_rowreg(s.Hpc, hq_j, i) + s.Rq[tid];
    __syncthreads();
    if (wid == 0) ldS0 = warp_gj_solve(s.S, s.Hpc, s.K, lane);
    __syncthreads();
    s.fc[tid] = s.pc[tid] - dot_rc(s.K, s.Hpc, i, j);
    s.G[tid] = s.Om0[tid];
    s.Go[tid] = s.Em[tid];
    if (tid < 16) s.fm[tid] = s.pm[tid] + mv(s.K, s.innov, tid);
    __syncthreads();

    // thread-0 scalar bookkeeping (doubles)
    double acc_sc = 0.0, ld_fc = 0.0, K0 = 0.0;
    if (tid == 0) {
        acc_sc = -0.5 * (16.0 * LOG2PI + (double)LDpr)
               - 0.5 * (16.0 * LOG2PI + (double)LDe);
        K0 = -8.0 * LOG2PI - 0.5 * (double)LDe - 0.5 * (double)LDp + 8.0;
        ld_fc = (double)ldqp + (double)LDRq - (double)ldS0;
    }
    double acc_el = 0.0;  // per-thread elementwise accumulation

    // ================= forward pass =================
    for (int t = 1; t < Tn; t++) {
        // RegA: M = Wq fc; pm; deferred G-update from previous step
        s.M[tid] = dot_rowreg_col(wq_i, s.fc, j);
        if (t > 1) s.G[tid] = dot_tc(s.bA, s.t2, i, j) + dot_tc(s.t1, s.OmpA, i, j);
        if (tid < 16) {
            s.pm[tid] = mv(s.Wq, s.fm, tid) + s.bq[tid];
            s.y[tid] = obs[t * 16 + tid];
        }
        __syncthreads();
        // RegB: pc = M Wq^T + Sq; innov
        s.pc[tid] = dot_row_rowreg(s.M, wq_j, i) + s.Sq[tid];
        if (tid < 16) s.innov[tid] = s.y[tid] - mv(s.Hq, s.pm, tid) - s.dq[tid];
        __syncthreads();
        // RegC: Hpc = Hq pc
        s.Hpc[tid] = dot_rowreg_col(hq_i, s.pc, j);
        __syncthreads();
        // RegD: S = Hpc Hq^T + Rq
        s.S[tid] = dot_row_rowreg(s.Hpc, hq_j, i) + s.Rq[tid];
        __syncthreads();
        // GJ: warp0 solves pc X = M (X^T = bA), warp1 solves S Y = Hpc (Y^T = K)
        if (wid == 0) {
            float ld = warp_gj_solve(s.pc, s.M, s.bA, lane);
            if (lane == 0) s.ld_a = ld;
        } else if (wid == 1) {
            float ld = warp_gj_solve(s.S, s.Hpc, s.K, lane);
            if (lane == 0) s.ld_b = ld;
        }
        __syncthreads();
        if (tid == 0) {
            double ldp = (double)s.ld_a, lds = (double)s.ld_b;
            acc_sc += K0 - 0.5 * (ldp - (double)LDSq - ld_fc);
            ld_fc = ldp + (double)LDRq - lds;
        }
        // RegE
        s.bcov[tid] = s.fc[tid] - dot_rc(s.bA, s.M, i, j);
        s.fcn[tid] = s.pc[tid] - dot_rc(s.K, s.Hpc, i, j);
        s.t1[tid] = dot_rc(s.Wp, s.bA, i, j) - ((i == j) ? 1.f : 0.f);
        s.t2[tid] = dot_rc(s.G, s.bA, i, j);
        s.t3[tid] = dot_rc(s.Go, s.bA, i, j);
        g_P[t][tid] = s.bA[tid];
        if (tid < 16) {
            g_ba[t][tid] = s.fm[tid] - mv(s.bA, s.pm, tid);
            s.fmn[tid] = s.pm[tid] + mv(s.K, s.innov, tid);
        }
        __syncthreads();
        // RegF
        acc_el += (double)((s.G[tid] + s.Go[tid] - 0.5f * s.Fm[tid]) * s.bcov[tid]);
        s.Go[tid] = dot_tc(s.bA, s.t3, i, j) + s.Em[tid];
        s.OmpA[tid] = dot_rc(s.Om_p, s.t1, i, j);
        s.fc[tid] = s.fcn[tid];
        if (tid < 16) s.fm[tid] = s.fmn[tid];
        __syncthreads();
    }
    if (tid == 0) acc_sc += 0.5 * (16.0 * LOG2PI + ld_fc) + 8.0;

    // ================= backward pass =================
    s.Rm[tid] = (i == j) ? 1.f : 0.f;
    {
        int t = Tn - 1;
        s.bA[tid] = g_P[t][tid];
        if (tid < 16) {
            s.vec0[tid] = g_ba[t][tid];
            s.y[tid] = obs[t * 16 + tid];
            s.u[tid] = 0.f;
        }
    }
    __syncthreads();

    for (int t = Tn - 1; t >= 0; t--) {
        // Reg1
        s.t1[tid] = (t > 0) ? (dot_rc(s.Wp, s.bA, i, j) - ((i == j) ? 1.f : 0.f))
                            : ((i == j) ? 1.f : 0.f);
        s.Ao[tid] = dot_rc(s.Wep, s.Rm, i, j);
        if (tid < 16) {
            s.vec1[tid] = (t > 0) ? (mv(s.Wp, s.vec0, tid) + s.bp[tid]) : (-s.ppm[tid]);
            s.vec2[tid] = mv(s.Wep, s.u, tid);
        }
        __syncthreads();
        // Reg2
        s.A[tid] = dot_rc(s.t1, s.Rm, i, j);
        if (t > 0) s.t3[tid] = dot_rc(s.bA, s.Rm, i, j);
        s.t2[tid] = dot_rc(s.Ao, s.fc, i, j);
        if (tid < 16) {
            s.vec1[tid] += mv(s.t1, s.u, tid);                       // B_final
            if (t > 0) s.vec3[tid] = s.vec0[tid] + mv(s.bA, s.u, tid);
            s.vec2[tid] = s.ebp[tid] - s.y[tid] + s.vec2[tid];       // Bo_final
        }
        __syncthreads();
        // Reg3
        s.M[tid] = dot_rc(s.A, s.fc, i, j);     // t0 = A fc
        s.pc[tid] = dot_rc(s.t2, s.Ao, i, j);   // No2 = Ao fc Ao^T
        if (tid < 16) {
            s.vec1[tid] = mv(s.A, s.fm, tid) + s.vec1[tid];   // cv
            s.vec2[tid] = mv(s.Ao, s.fm, tid) + s.vec2[tid];  // co
        }
        __syncthreads();
        // Reg4 (+ preload for next iteration)
        {
            float Sm = dot_rc(s.M, s.A, i, j);
            const float* Om = (t == 0) ? s.Om0 : s.Om_p;
            float val = Om[tid] * (Sm + s.vec1[i] * s.vec1[j])
                      + s.om[tid] * (s.pc[tid] + s.vec2[i] * s.vec2[j]);
            acc_el += (double)val;
        }
        if (t > 0) {
            s.Rm[tid] = s.t3[tid];
            s.bA[tid] = g_P[t - 1][tid];
            if (tid < 16) {
                s.u[tid] = s.vec3[tid];
                s.vec0[tid] = g_ba[t - 1][tid];
                s.y[tid] = obs[(t - 1) * 16 + tid];
            }
        }
        __syncthreads();
    }

    // ---- final reduction ----
    double v = acc_el;
#pragma unroll
    for (int o = 16; o; o >>= 1) v += __shfl_xor_sync(0xffffffffu, v, o);
    if (lane == 0) s.dred[wid] = v;
    __syncthreads();
    if (tid == 0) {
        double tot = acc_sc;
#pragma unroll
        for (int w = 0; w < 8; w++) tot += s.dred[w];
        out[0] = (float)tot;
    }
}

extern "C" void kernel_launch(void* const* d_in, const int* in_sizes, int n_in,
                              void* d_out, int out_size) {
    int Tn = in_sizes[0] / 16;
    if (Tn > TMAX) Tn = TMAX;
    lgq_kernel<<<1, 256>>>(
        (const float*)d_in[0], (const float*)d_in[1], (const float*)d_in[2],
        (const float*)d_in[3], (const float*)d_in[4], (const float*)d_in[5],
        (const float*)d_in[6], (const float*)d_in[7], (const float*)d_in[8],
        (const float*)d_in[9], (const float*)d_in[10], (const float*)d_in[11],
        (const float*)d_in[12], (const float*)d_in[13], (const float*)d_in[14],
        (const float*)d_in[15], (const float*)d_in[16], (float*)d_out, Tn);
}

// round 4
// speedup vs baseline: 3.5126x; 1.8164x over previous
#include <cuda_runtime.h>
#include <math.h>

#define TMAX 256
#define LOG2PI 1.8378770664093453

// ---------------- device scratch ----------------
__device__ float g_P[TMAX][256];
__device__ float g_ba[TMAX][16];
__device__ float g_Lr[TMAX][256];
__device__ float g_Lu[TMAX][16];
__device__ float g_Sr[16][256];
__device__ float g_Su[16][16];
__device__ float g_Gr[16][256];
__device__ float g_Gu[16][16];
__device__ float g_OmP[256], g_om[256], g_Om0[256];
__device__ float g_fcF[256], g_fmF[16];
__device__ double g_part[17];

#define BARA() asm volatile("bar.sync 1, 128;" ::: "memory")
#define BARB() asm volatile("bar.sync 2, 128;" ::: "memory")
#define BAR0() asm volatile("bar.sync 0, 256;" ::: "memory")

// ---------------- dot helpers ----------------
__device__ __forceinline__ float dot_rc(const float* A, const float* B, int i, int j) {
    float s = 0.f;
#pragma unroll
    for (int k = 0; k < 16; k++) s = fmaf(A[i * 16 + k], B[k * 16 + j], s);
    return s;
}
__device__ __forceinline__ float dot_tc(const float* A, const float* B, int i, int j) { // A^T B
    float s = 0.f;
#pragma unroll
    for (int k = 0; k < 16; k++) s = fmaf(A[k * 16 + i], B[k * 16 + j], s);
    return s;
}
__device__ __forceinline__ float dot_rt(const float* A, const float* B, int i, int j) { // A B^T
    float s = 0.f;
#pragma unroll
    for (int k = 0; k < 16; k++) s = fmaf(A[i * 16 + k], B[j * 16 + k], s);
    return s;
}
__device__ __forceinline__ float dot_rowreg_col(const float* row, const float* B, int j) {
    float s = 0.f;
#pragma unroll
    for (int k = 0; k < 16; k++) s = fmaf(row[k], B[k * 16 + j], s);
    return s;
}
__device__ __forceinline__ float dot_rr(const float* Arow, const float* rowreg) {
    float s = 0.f;
#pragma unroll
    for (int k = 0; k < 16; k++) s = fmaf(Arow[k], rowreg[k], s);
    return s;
}
__device__ __forceinline__ float mv(const float* M, const float* v, int r) {
    float s = 0.f;
#pragma unroll
    for (int k = 0; k < 16; k++) s = fmaf(M[r * 16 + k], v[k], s);
    return s;
}

// Single-warp register-resident Gauss-Jordan solve: A (16x16 SPD) X = B.
// Lane l<16 owns column l of A; lane l>=16 owns column l-16 of B.
// Writes X^T (row-major) to Xt. Returns logdet(A) on all lanes.
__device__ __forceinline__ float warp_gj_solve(const float* Am, const float* Bm,
                                               float* Xt, int lane) {
    float a[16];
    {
        const float* src = (lane < 16) ? (Am + lane) : (Bm + lane - 16);
#pragma unroll
        for (int r = 0; r < 16; r++) a[r] = src[r * 16];
    }
    float mypiv = 1.f;
#pragma unroll
    for (int p = 0; p < 16; p++) {
        float f[16];
#pragma unroll
        for (int r = 0; r < 16; r++) f[r] = __shfl_sync(0xffffffffu, a[r], p);
        float x = f[p];
        if (lane == p) mypiv = x;
        float r0;
        asm("rcp.approx.f32 %0, %1;" : "=f"(r0) : "f"(x));
        float pivinv = r0 * (2.0f - x * r0);
        a[p] *= pivinv;
#pragma unroll
        for (int r = 0; r < 16; r++)
            if (r != p) a[r] = fmaf(-f[r], a[p], a[r]);
    }
    float lg = __logf(mypiv);
#pragma unroll
    for (int o = 16; o; o >>= 1) lg += __shfl_xor_sync(0xffffffffu, lg, o);
    if (lane >= 16) {
        float4* dst = reinterpret_cast<float4*>(Xt + (lane - 16) * 16);
        dst[0] = make_float4(a[0], a[1], a[2], a[3]);
        dst[1] = make_float4(a[4], a[5], a[6], a[7]);
        dst[2] = make_float4(a[8], a[9], a[10], a[11]);
        dst[3] = make_float4(a[12], a[13], a[14], a[15]);
    }
    return lg;
}

// ---------------- forward kernel ----------------
struct SMF {
    float Wq[256], Sq[256], Hq[256], Rq[256], Wp[256], Wep[256];
    float Om_p[256], om[256], Om0[256], Em[256], Fm[256];
    float fcb[2][256], M[2][256], pc[2][256];
    float Hpc[256], S[256], K[256];
    float bA[256], t1[256], t2[256], t3[256], OmpA[256], G[256], Go[256];
    float bq[16], dq[16], bp[16], ebp[16], ppm[16];
    float fmb[2][16], pm[2][16], innov[16], y[16];
    double dred[8], dsc[2];
};

__global__ void __launch_bounds__(256, 1) lgq_fwd(
    const float* obs, const float* p_prior_mean, const float* p_prior_cov,
    const float* p_trans_w, const float* p_trans_b, const float* p_trans_cov,
    const float* p_emis_w, const float* p_emis_b, const float* p_emis_cov,
    const float* q_prior_mean, const float* q_prior_cov, const float* q_trans_w,
    const float* q_trans_b, const float* q_trans_cov, const float* q_emis_w,
    const float* q_emis_b, const float* q_emis_cov, int Tn) {
    __shared__ SMF s;
    const int tid = threadIdx.x;
    const int i = tid >> 4, j = tid & 15;
    const int lane = tid & 31, wid = tid >> 5;

    // load constants
    s.Wq[tid] = q_trans_w[tid];
    s.Sq[tid] = q_trans_cov[tid];
    s.Hq[tid] = q_emis_w[tid];
    s.Rq[tid] = q_emis_cov[tid];
    s.Wp[tid] = p_trans_w[tid];
    s.Wep[tid] = p_emis_w[tid];
    if (tid < 16) {
        s.bq[tid] = q_trans_b[tid];
        s.dq[tid] = q_emis_b[tid];
        s.bp[tid] = p_trans_b[tid];
        s.ebp[tid] = p_emis_b[tid];
        s.ppm[tid] = p_prior_mean[tid];
    }
    __syncthreads();

    // ---- setup: constant inverses / logdets ----
    float LDp = 0.f, LDe = 0.f, LDpr = 0.f, LDSq = 0.f, LDRq = 0.f, ldqp = 0.f, ldS0 = 0.f;
    s.t2[tid] = (i == j) ? 1.f : 0.f;  // identity RHS (GJ never writes inputs)
    s.S[tid] = p_trans_cov[tid];
    __syncthreads();
    if (wid == 0) LDp = warp_gj_solve(s.S, s.t2, s.K, lane);
    __syncthreads();
    s.Om_p[tid] = -0.5f * s.K[tid];
    s.t3[tid] = dot_rc(s.K, s.Wp, i, j);
    __syncthreads();
    s.Fm[tid] = dot_tc(s.Wp, s.t3, i, j);
    s.S[tid] = p_emis_cov[tid];
    __syncthreads();
    if (wid == 0) LDe = warp_gj_solve(s.S, s.t2, s.K, lane);
    __syncthreads();
    s.om[tid] = -0.5f * s.K[tid];
    s.S[tid] = p_prior_cov[tid];
    __syncthreads();
    s.t3[tid] = dot_rc(s.om, s.Wep, i, j);
    if (wid == 0) LDpr = warp_gj_solve(s.S, s.t2, s.K, lane);
    __syncthreads();
    s.Em[tid] = dot_tc(s.Wep, s.t3, i, j);
    s.Om0[tid] = -0.5f * s.K[tid];
    s.S[tid] = q_trans_cov[tid];
    __syncthreads();
    if (wid == 0) LDSq = warp_gj_solve(s.S, s.t2, s.t3, lane);
    __syncthreads();
    s.S[tid] = q_emis_cov[tid];
    __syncthreads();
    if (wid == 0) LDRq = warp_gj_solve(s.S, s.t2, s.t3, lane);
    __syncthreads();

    // ---- t=0 Kalman update ----
    s.pc[0][tid] = q_prior_cov[tid];
    if (tid < 16) {
        s.pm[0][tid] = q_prior_mean[tid];
        s.y[tid] = obs[tid];
    }
    __syncthreads();
    if (wid == 0) ldqp = warp_gj_solve(s.pc[0], s.t2, s.t3, lane);
    __syncthreads();
    s.Hpc[tid] = dot_rc(s.Hq, s.pc[0], i, j);
    if (tid < 16) s.innov[tid] = s.y[tid] - mv(s.Hq, s.pm[0], tid) - s.dq[tid];
    __syncthreads();
    s.S[tid] = dot_rt(s.Hpc, s.Hq, i, j) + s.Rq[tid];
    __syncthreads();
    if (wid == 0) ldS0 = warp_gj_solve(s.S, s.Hpc, s.K, lane);
    __syncthreads();
    s.fcb[0][tid] = s.pc[0][tid] - dot_rc(s.K, s.Hpc, i, j);
    s.G[tid] = s.Om0[tid];
    s.Go[tid] = s.Em[tid];
    if (tid < 16) s.fmb[0][tid] = s.pm[0][tid] + mv(s.K, s.innov, tid);
    __syncthreads();

    // thread-0 setup scalars
    double set_acc = 0.0, K0d = 0.0, ldfc0 = 0.0, LDSqd = 0.0, LDRqd = 0.0;
    if (tid == 0) {
        set_acc = -0.5 * (16.0 * LOG2PI + (double)LDpr)
                - 0.5 * (16.0 * LOG2PI + (double)LDe);
        K0d = -8.0 * LOG2PI - 0.5 * (double)LDe - 0.5 * (double)LDp + 8.0;
        ldfc0 = (double)ldqp + (double)LDRq - (double)ldS0;  // logdet(fc_0)
        LDSqd = (double)LDSq;
        LDRqd = (double)LDRq;
    }

    double accel = 0.0, d0 = 0.0;
    float lastld = 0.f;

    // ================= split pipeline =================
    if (tid < 128) {
        // -------- group A: Kalman recursion --------
        const int l = tid;
        const int ia0 = l >> 4, ia1 = ia0 + 8, ja = l & 15;
        const int e0 = ia0 * 16 + ja, e1 = ia1 * 16 + ja;
        float wqi0[16], wqi1[16], wqj[16], hqi0[16], hqi1[16], hqj[16];
#pragma unroll
        for (int k = 0; k < 16; k++) {
            wqi0[k] = s.Wq[ia0 * 16 + k];
            wqi1[k] = s.Wq[ia1 * 16 + k];
            wqj[k] = s.Wq[ja * 16 + k];
            hqi0[k] = s.Hq[ia0 * 16 + k];
            hqi1[k] = s.Hq[ia1 * 16 + k];
            hqj[k] = s.Hq[ja * 16 + k];
        }
        for (int t = 1; t < Tn; t++) {
            const int w = t & 1, r = w ^ 1;
            // A1: M = Wq fc; pm
            s.M[w][e0] = dot_rowreg_col(wqi0, s.fcb[r], ja);
            s.M[w][e1] = dot_rowreg_col(wqi1, s.fcb[r], ja);
            if (l < 16) {
                s.pm[w][l] = mv(s.Wq, s.fmb[r], l) + s.bq[l];
                s.y[l] = obs[t * 16 + l];
            }
            BARA();
            // A2: pc = M Wq^T + Sq; innov
            s.pc[w][e0] = dot_rr(s.M[w] + ia0 * 16, wqj) + s.Sq[e0];
            s.pc[w][e1] = dot_rr(s.M[w] + ia1 * 16, wqj) + s.Sq[e1];
            if (l < 16) s.innov[l] = s.y[l] - mv(s.Hq, s.pm[w], l) - s.dq[l];
            BAR0();  // publish pc, M, pm to group B
            // A3: Hpc = Hq pc
            s.Hpc[e0] = dot_rowreg_col(hqi0, s.pc[w], ja);
            s.Hpc[e1] = dot_rowreg_col(hqi1, s.pc[w], ja);
            BARA();
            // A4: S = Hpc Hq^T + Rq
            s.S[e0] = dot_rr(s.Hpc + ia0 * 16, hqj) + s.Rq[e0];
            s.S[e1] = dot_rr(s.Hpc + ia1 * 16, hqj) + s.Rq[e1];
            BARA();
            // A5: GJ(S, Hpc) -> K on warp 0
            if (wid == 0) {
                float ld = warp_gj_solve(s.S, s.Hpc, s.K, lane);
                d0 += (double)ld;  // sum lds
                lastld = ld;       // lds_N
            }
            BARA();
            // A6: fc' = pc - K Hpc; fm' = pm + K innov
            s.fcb[w][e0] = s.pc[w][e0] - dot_rc(s.K, s.Hpc, ia0, ja);
            s.fcb[w][e1] = s.pc[w][e1] - dot_rc(s.K, s.Hpc, ia1, ja);
            if (l < 16) s.fmb[w][l] = s.pm[w][l] + mv(s.K, s.innov, l);
            BARA();
        }
    } else {
        // -------- group B: side chain --------
        const int l = tid - 128;
        const int ib0 = l >> 4, ib1 = ib0 + 8, jb = l & 15;
        const int e0 = ib0 * 16 + jb, e1 = ib1 * 16 + jb;
        float wpi0[16], wpi1[16];
#pragma unroll
        for (int k = 0; k < 16; k++) {
            wpi0[k] = s.Wp[ib0 * 16 + k];
            wpi1[k] = s.Wp[ib1 * 16 + k];
        }
        for (int t = 1; t < Tn; t++) {
            const int w = t & 1, r = w ^ 1;
            BAR0();  // wait for pc, M, pm of step t
            // B1: GJ(pc, M) -> bA on warp 5
            if (wid == 5) {
                float ld = warp_gj_solve(s.pc[w], s.M[w], s.bA, lane);
                d0 += (double)ld;  // sum ldp
                lastld = ld;       // ldp_N
            }
            BARB();
            // B2: t1 = Wp bA - I; t2 = G bA; t3 = Go bA; stores
            s.t1[e0] = dot_rowreg_col(wpi0, s.bA, jb) - ((ib0 == jb) ? 1.f : 0.f);
            s.t1[e1] = dot_rowreg_col(wpi1, s.bA, jb) - ((ib1 == jb) ? 1.f : 0.f);
            s.t2[e0] = dot_rc(s.G, s.bA, ib0, jb);
            s.t2[e1] = dot_rc(s.G, s.bA, ib1, jb);
            s.t3[e0] = dot_rc(s.Go, s.bA, ib0, jb);
            s.t3[e1] = dot_rc(s.Go, s.bA, ib1, jb);
            g_P[t][e0] = s.bA[e0];
            g_P[t][e1] = s.bA[e1];
            if (l < 16) g_ba[t][l] = s.fmb[r][l] - mv(s.bA, s.pm[w], l);
            BARB();
            // B3: OmpA = Om_p t1; bcov elementwise; accumulate
            s.OmpA[e0] = dot_rc(s.Om_p, s.t1, ib0, jb);
            s.OmpA[e1] = dot_rc(s.Om_p, s.t1, ib1, jb);
            {
                float bc0 = s.fcb[r][e0] - dot_rc(s.bA, s.M[w], ib0, jb);
                float bc1 = s.fcb[r][e1] - dot_rc(s.bA, s.M[w], ib1, jb);
                accel += (double)((s.G[e0] + s.Go[e0] - 0.5f * s.Fm[e0]) * bc0)
                       + (double)((s.G[e1] + s.Go[e1] - 0.5f * s.Fm[e1]) * bc1);
            }
            BARB();
            // B4: G' = bA^T t2 + t1^T OmpA; Go' = bA^T t3 + Em
            {
                float g0 = dot_tc(s.bA, s.t2, ib0, jb) + dot_tc(s.t1, s.OmpA, ib0, jb);
                float g1 = dot_tc(s.bA, s.t2, ib1, jb) + dot_tc(s.t1, s.OmpA, ib1, jb);
                float go0 = dot_tc(s.bA, s.t3, ib0, jb) + s.Em[e0];
                float go1 = dot_tc(s.bA, s.t3, ib1, jb) + s.Em[e1];
                s.G[e0] = g0;
                s.G[e1] = g1;
                s.Go[e0] = go0;
                s.Go[e1] = go1;
            }
            BARB();
        }
    }
    __syncthreads();

    // ---- epilogue: publish constants + final state + partial sums ----
    g_OmP[tid] = s.Om_p[tid];
    g_om[tid] = s.om[tid];
    g_Om0[tid] = s.Om0[tid];
    {
        int fp = (Tn - 1) & 1;
        g_fcF[tid] = s.fcb[fp][tid];
        if (tid < 16) g_fmF[tid] = s.fmb[fp][tid];
    }
    double v = accel;
#pragma unroll
    for (int o = 16; o; o >>= 1) v += __shfl_xor_sync(0xffffffffu, v, o);
    if (lane == 0) s.dred[wid] = v;
    if (tid == 160) {
        s.dsc[0] = d0;               // SP = sum ldp_t
        s.dsc[1] = (double)lastld;   // ldp_N
    }
    __syncthreads();
    if (tid == 0) {
        double elem = 0.0;
#pragma unroll
        for (int w = 0; w < 8; w++) elem += s.dred[w];
        double SP = s.dsc[0], ldpN = s.dsc[1];
        double sumS = d0, ldsN = (double)lastld;
        double N = (double)(Tn - 1);
        // F_t = logdet(fc_t) = ldp_t + LDRq - lds_t (memoryless), F_0 = ldfc0.
        // sum_{t=1..N} F_{t-1} = ldfc0 + (SP - ldpN) + (N-1)*LDRq - (sumS - ldsN)
        double sumF = ldfc0 + (SP - ldpN) + (N - 1.0) * LDRqd - (sumS - ldsN);
        double FN = ldpN + LDRqd - ldsN;
        double sc = set_acc
                  + N * (K0d + 0.5 * LDSqd)
                  - 0.5 * SP
                  + 0.5 * sumF
                  + 0.5 * (16.0 * LOG2PI + FN) + 8.0
                  + elem;
        g_part[16] = sc;
    }
}

// ---------------- backward scan kernels ----------------
__global__ void __launch_bounds__(256, 1) lgq_scan1(int Tn) {
    const int b = blockIdx.x;
    const int lo = b * 16;
    int hi = lo + 16;
    if (hi > Tn) hi = Tn;
    __shared__ float R[256], Rn[256], bA[256];
    __shared__ float u[16], un[16], ba[16];
    const int tid = threadIdx.x;
    const int i = tid >> 4, j = tid & 15;
    R[tid] = (i == j) ? 1.f : 0.f;
    if (tid < 16) u[tid] = 0.f;
    __syncthreads();
    for (int t = hi - 1; t >= lo; t--) {
        g_Lr[t][tid] = R[tid];
        if (tid < 16) g_Lu[t][tid] = u[tid];
        if (t == 0) break;
        bA[tid] = g_P[t][tid];
        if (tid < 16) ba[tid] = g_ba[t][tid];
        __syncthreads();
        Rn[tid] = dot_rc(bA, R, i, j);
        if (tid < 16) un[tid] = ba[tid] + mv(bA, u, tid);
        __syncthreads();
        R[tid] = Rn[tid];
        if (tid < 16) u[tid] = un[tid];
        __syncthreads();
    }
    g_Sr[b][tid] = R[tid];
    if (tid < 16) g_Su[b][tid] = u[tid];
}

__global__ void __launch_bounds__(256, 1) lgq_scan2(int Tn) {
    const int nseg = (Tn + 15) / 16;
    __shared__ float Gr[256], Gn[256], Sr[256];
    __shared__ float Gu[16], gn[16], Su[16];
    const int tid = threadIdx.x;
    const int i = tid >> 4, j = tid & 15;
    Gr[tid] = (i == j) ? 1.f : 0.f;
    if (tid < 16) Gu[tid] = 0.f;
    __syncthreads();
    for (int b = nseg - 1; b >= 0; b--) {
        g_Gr[b][tid] = Gr[tid];
        if (tid < 16) g_Gu[b][tid] = Gu[tid];
        if (b == 0) break;
        Sr[tid] = g_Sr[b][tid];
        if (tid < 16) Su[tid] = g_Su[b][tid];
        __syncthreads();
        Gn[tid] = dot_rc(Sr, Gr, i, j);
        if (tid < 16) gn[tid] = mv(Sr, Gu, tid) + Su[tid];
        __syncthreads();
        Gr[tid] = Gn[tid];
        if (tid < 16) Gu[tid] = gn[tid];
        __syncthreads();
    }
}

__global__ void __launch_bounds__(256, 1) lgq_scan3(
    const float* obs, const float* p_trans_w, const float* p_trans_b,
    const float* p_emis_w, const float* p_emis_b, const float* p_prior_mean,
    int Tn) {
    const int b = blockIdx.x;
    const int lo = b * 16;
    int hi = lo + 16;
    if (hi > Tn) hi = Tn;
    __shared__ float OmP[256], omm[256], Om0[256], Wp[256], Wep[256], fc[256], Gr[256];
    __shared__ float Lr[256], bA[256], Rf[256], Ai[256], A[256], Ao[256], AF[256], AoF[256];
    __shared__ float fm[16], Gu[16], Lu[16], bav[16], uf[16], Bv[16], Bo[16];
    __shared__ float cv[16], co[16], y[16], bp[16], ebp[16], ppm[16];
    __shared__ double dred[8];
    const int tid = threadIdx.x;
    const int i = tid >> 4, j = tid & 15;
    const int lane = tid & 31, wid = tid >> 5;

    OmP[tid] = g_OmP[tid];
    omm[tid] = g_om[tid];
    Om0[tid] = g_Om0[tid];
    Wp[tid] = p_trans_w[tid];
    Wep[tid] = p_emis_w[tid];
    fc[tid] = g_fcF[tid];
    Gr[tid] = g_Gr[b][tid];
    if (tid < 16) {
        fm[tid] = g_fmF[tid];
        Gu[tid] = g_Gu[b][tid];
        bp[tid] = p_trans_b[tid];
        ebp[tid] = p_emis_b[tid];
        ppm[tid] = p_prior_mean[tid];
    }
    __syncthreads();

    double acc = 0.0;
    for (int t = lo; t < hi; t++) {
        // st0: stage loads
        Lr[tid] = g_Lr[t][tid];
        bA[tid] = (t > 0) ? g_P[t][tid] : 0.f;
        if (tid < 16) {
            Lu[tid] = g_Lu[t][tid];
            bav[tid] = (t > 0) ? g_ba[t][tid] : 0.f;
            y[tid] = obs[t * 16 + tid];
        }
        __syncthreads();
        // st1: Rf = Lr Gr; Ai; uf; Bv init
        Rf[tid] = dot_rc(Lr, Gr, i, j);
        Ai[tid] = (t > 0) ? (dot_rc(Wp, bA, i, j) - ((i == j) ? 1.f : 0.f))
                          : ((i == j) ? 1.f : 0.f);
        if (tid < 16) {
            uf[tid] = mv(Lr, Gu, tid) + Lu[tid];
            Bv[tid] = (t > 0) ? (mv(Wp, bav, tid) + bp[tid]) : (-ppm[tid]);
        }
        __syncthreads();
        // st2: A = Ai Rf; Ao = Wep Rf; B vectors
        A[tid] = dot_rc(Ai, Rf, i, j);
        Ao[tid] = dot_rc(Wep, Rf, i, j);
        if (tid < 16) {
            Bv[tid] += mv(Ai, uf, tid);
            Bo[tid] = ebp[tid] - y[tid] + mv(Wep, uf, tid);
        }
        __syncthreads();
        // st3: AF = A fc; AoF = Ao fc; cv, co
        AF[tid] = dot_rc(A, fc, i, j);
        AoF[tid] = dot_rc(Ao, fc, i, j);
        if (tid < 16) {
            cv[tid] = mv(A, fm, tid) + Bv[tid];
            co[tid] = mv(Ao, fm, tid) + Bo[tid];
        }
        __syncthreads();
        // st4: accumulate
        {
            const float* Om = (t == 0) ? Om0 : OmP;
            float val = Om[tid] * (dot_rc(AF, A, i, j) + cv[i] * cv[j])
                      + omm[tid] * (dot_rc(AoF, Ao, i, j) + co[i] * co[j]);
            acc += (double)val;
        }
        __syncthreads();
    }

    double v = acc;
#pragma unroll
    for (int o = 16; o; o >>= 1) v += __shfl_xor_sync(0xffffffffu, v, o);
    if (lane == 0) dred[wid] = v;
    __syncthreads();
    if (tid == 0) {
        double tot = 0.0;
#pragma unroll
        for (int w = 0; w < 8; w++) tot += dred[w];
        g_part[b] = tot;
    }
}

__global__ void lgq_fin(float* out, int Tn) {
    if (threadIdx.x == 0) {
        const int nseg = (Tn + 15) / 16;
        double tot = g_part[16];
        for (int b = 0; b < nseg; b++) tot += g_part[b];
        out[0] = (float)tot;
    }
}

extern "C" void kernel_launch(void* const* d_in, const int* in_sizes, int n_in,
                              void* d_out, int out_size) {
    int Tn = in_sizes[0] / 16;
    if (Tn > TMAX) Tn = TMAX;
    const int nseg = (Tn + 15) / 16;
    lgq_fwd<<<1, 256>>>(
        (const float*)d_in[0], (const float*)d_in[1], (const float*)d_in[2],
        (const float*)d_in[3], (const float*)d_in[4], (const float*)d_in[5],
        (const float*)d_in[6], (const float*)d_in[7], (const float*)d_in[8],
        (const float*)d_in[9], (const float*)d_in[10], (const float*)d_in[11],
        (const float*)d_in[12], (const float*)d_in[13], (const float*)d_in[14],
        (const float*)d_in[15], (const float*)d_in[16], Tn);
    lgq_scan1<<<nseg, 256>>>(Tn);
    lgq_scan2<<<1, 256>>>(Tn);
    lgq_scan3<<<nseg, 256>>>(
        (const float*)d_in[0], (const float*)d_in[3], (const float*)d_in[4],
        (const float*)d_in[6], (const float*)d_in[7], (const float*)d_in[1], Tn);
    lgq_fin<<<1, 32>>>((float*)d_out, Tn);
}

// round 5
// speedup vs baseline: 3.5450x; 1.0092x over previous
#include <cuda_runtime.h>
#include <math.h>

#define TMAX 256
#define LOG2PI 1.8378770664093453

// ---------------- device scratch ----------------
__device__ float g_P[TMAX][256];
__device__ float g_ba[TMAX][16];
__device__ float g_Lr[TMAX][256];
__device__ float g_Lu[TMAX][16];
__device__ float g_Sr[32][256];
__device__ float g_Su[32][16];
__device__ float g_Gr[32][256];
__device__ float g_Gu[32][16];
__device__ float g_OmP[256], g_om[256], g_Om0[256];
__device__ float g_fcF[256], g_fmF[16];
__device__ double g_part[65];

#define BARA() asm volatile("bar.sync 1, 128;" ::: "memory")
#define BARB() asm volatile("bar.sync 2, 128;" ::: "memory")
#define BAR0() asm volatile("bar.sync 0, 256;" ::: "memory")

// ---------------- dot helpers ----------------
__device__ __forceinline__ float dot_rc(const float* A, const float* B, int i, int j) {
    float s = 0.f;
#pragma unroll
    for (int k = 0; k < 16; k++) s = fmaf(A[i * 16 + k], B[k * 16 + j], s);
    return s;
}
__device__ __forceinline__ float dot_tc(const float* A, const float* B, int i, int j) { // A^T B
    float s = 0.f;
#pragma unroll
    for (int k = 0; k < 16; k++) s = fmaf(A[k * 16 + i], B[k * 16 + j], s);
    return s;
}
__device__ __forceinline__ float dot_rt(const float* A, const float* B, int i, int j) { // A B^T
    float s = 0.f;
#pragma unroll
    for (int k = 0; k < 16; k++) s = fmaf(A[i * 16 + k], B[j * 16 + k], s);
    return s;
}
__device__ __forceinline__ float dot_rowreg_col(const float* row, const float* B, int j) {
    float s = 0.f;
#pragma unroll
    for (int k = 0; k < 16; k++) s = fmaf(row[k], B[k * 16 + j], s);
    return s;
}
__device__ __forceinline__ float dot_rr(const float* a, const float* b) {
    float s = 0.f;
#pragma unroll
    for (int k = 0; k < 16; k++) s = fmaf(a[k], b[k], s);
    return s;
}
__device__ __forceinline__ float mv(const float* M, const float* v, int r) {
    float s = 0.f;
#pragma unroll
    for (int k = 0; k < 16; k++) s = fmaf(M[r * 16 + k], v[k], s);
    return s;
}

// Single-warp register-resident Gauss-Jordan solve: A (16x16 SPD) X = B.
// Lane l<16 owns column l of A; lane l>=16 owns column l-16 of B.
// Writes X^T (row-major) to Xt. Returns logdet(A) on all lanes.
__device__ __forceinline__ float warp_gj_solve(const float* Am, const float* Bm,
                                               float* Xt, int lane) {
    float a[16];
    {
        const float* src = (lane < 16) ? (Am + lane) : (Bm + lane - 16);
#pragma unroll
        for (int r = 0; r < 16; r++) a[r] = src[r * 16];
    }
    float mypiv = 1.f;
#pragma unroll
    for (int p = 0; p < 16; p++) {
        float f[16];
#pragma unroll
        for (int r = 0; r < 16; r++) f[r] = __shfl_sync(0xffffffffu, a[r], p);
        float x = f[p];
        if (lane == p) mypiv = x;
        float r0;
        asm("rcp.approx.f32 %0, %1;" : "=f"(r0) : "f"(x));
        float pivinv = r0 * (2.0f - x * r0);
        a[p] *= pivinv;
#pragma unroll
        for (int r = 0; r < 16; r++)
            if (r != p) a[r] = fmaf(-f[r], a[p], a[r]);
    }
    float lg = __logf(mypiv);
#pragma unroll
    for (int o = 16; o; o >>= 1) lg += __shfl_xor_sync(0xffffffffu, lg, o);
    if (lane >= 16) {
        float4* dst = reinterpret_cast<float4*>(Xt + (lane - 16) * 16);
        dst[0] = make_float4(a[0], a[1], a[2], a[3]);
        dst[1] = make_float4(a[4], a[5], a[6], a[7]);
        dst[2] = make_float4(a[8], a[9], a[10], a[11]);
        dst[3] = make_float4(a[12], a[13], a[14], a[15]);
    }
    return lg;
}

// ---------------- forward kernel ----------------
struct SMF {
    float Wq[256], Sq[256], Hq[256], Rq[256], Wp[256], Wep[256];
    float WH[256], C1[256], C2[256];
    float Om_p[256], om[256], Om0[256], Em[256], Fm[256];
    float fcb[2][256], M[2][256], pc[2][256];
    float U[256], Hpc[256], S[256], K[256];
    float bA[256], t1[256], t2[256], t3[256], OmpA[256], G[256], Go[256];
    float bq[16], dq[16], bp[16], ebp[16], ppm[16];
    float fmb[2][16], pm[2][16], innov[16], y[16];
    double dred[8], dsc[2];
};

__global__ void __launch_bounds__(256, 1) lgq_fwd(
    const float* obs, const float* p_prior_mean, const float* p_prior_cov,
    const float* p_trans_w, const float* p_trans_b, const float* p_trans_cov,
    const float* p_emis_w, const float* p_emis_b, const float* p_emis_cov,
    const float* q_prior_mean, const float* q_prior_cov, const float* q_trans_w,
    const float* q_trans_b, const float* q_trans_cov, const float* q_emis_w,
    const float* q_emis_b, const float* q_emis_cov, int Tn) {
    __shared__ SMF s;
    const int tid = threadIdx.x;
    const int i = tid >> 4, j = tid & 15;
    const int lane = tid & 31, wid = tid >> 5;

    // load constants
    s.Wq[tid] = q_trans_w[tid];
    s.Sq[tid] = q_trans_cov[tid];
    s.Hq[tid] = q_emis_w[tid];
    s.Rq[tid] = q_emis_cov[tid];
    s.Wp[tid] = p_trans_w[tid];
    s.Wep[tid] = p_emis_w[tid];
    if (tid < 16) {
        s.bq[tid] = q_trans_b[tid];
        s.dq[tid] = q_emis_b[tid];
        s.bp[tid] = p_trans_b[tid];
        s.ebp[tid] = p_emis_b[tid];
        s.ppm[tid] = p_prior_mean[tid];
    }
    __syncthreads();

    // fused-stage constants: WH = Hq Wq; C1 = Hq Sq; C2 = C1 Hq^T + Rq
    s.WH[tid] = dot_rc(s.Hq, s.Wq, i, j);
    s.C1[tid] = dot_rc(s.Hq, s.Sq, i, j);

    // ---- setup: constant inverses / logdets ----
    float LDp = 0.f, LDe = 0.f, LDpr = 0.f, LDSq = 0.f, LDRq = 0.f, ldqp = 0.f, ldS0 = 0.f;
    s.t2[tid] = (i == j) ? 1.f : 0.f;  // identity RHS (GJ never writes inputs)
    s.S[tid] = p_trans_cov[tid];
    __syncthreads();
    s.C2[tid] = dot_rt(s.C1, s.Hq, i, j) + s.Rq[tid];
    if (wid == 0) LDp = warp_gj_solve(s.S, s.t2, s.K, lane);
    __syncthreads();
    s.Om_p[tid] = -0.5f * s.K[tid];
    s.t3[tid] = dot_rc(s.K, s.Wp, i, j);
    __syncthreads();
    s.Fm[tid] = dot_tc(s.Wp, s.t3, i, j);
    s.S[tid] = p_emis_cov[tid];
    __syncthreads();
    if (wid == 0) LDe = warp_gj_solve(s.S, s.t2, s.K, lane);
    __syncthreads();
    s.om[tid] = -0.5f * s.K[tid];
    s.S[tid] = p_prior_cov[tid];
    __syncthreads();
    s.t3[tid] = dot_rc(s.om, s.Wep, i, j);
    if (wid == 0) LDpr = warp_gj_solve(s.S, s.t2, s.K, lane);
    __syncthreads();
    s.Em[tid] = dot_tc(s.Wep, s.t3, i, j);
    s.Om0[tid] = -0.5f * s.K[tid];
    s.S[tid] = q_trans_cov[tid];
    __syncthreads();
    if (wid == 0) LDSq = warp_gj_solve(s.S, s.t2, s.t3, lane);
    __syncthreads();
    s.S[tid] = q_emis_cov[tid];
    __syncthreads();
    if (wid == 0) LDRq = warp_gj_solve(s.S, s.t2, s.t3, lane);
    __syncthreads();

    // ---- t=0 Kalman update (pc = q_prior_cov) ----
    s.pc[0][tid] = q_prior_cov[tid];
    if (tid < 16) {
        s.pm[0][tid] = q_prior_mean[tid];
        s.y[tid] = obs[tid];
    }
    __syncthreads();
    if (wid == 0) ldqp = warp_gj_solve(s.pc[0], s.t2, s.t3, lane);
    __syncthreads();
    s.Hpc[tid] = dot_rc(s.Hq, s.pc[0], i, j);
    if (tid < 16) s.innov[tid] = s.y[tid] - mv(s.Hq, s.pm[0], tid) - s.dq[tid];
    __syncthreads();
    s.S[tid] = dot_rt(s.Hpc, s.Hq, i, j) + s.Rq[tid];
    __syncthreads();
    if (wid == 0) ldS0 = warp_gj_solve(s.S, s.Hpc, s.K, lane);
    __syncthreads();
    s.fcb[0][tid] = s.pc[0][tid] - dot_rc(s.K, s.Hpc, i, j);
    s.G[tid] = s.Om0[tid];
    s.Go[tid] = s.Em[tid];
    if (tid < 16) s.fmb[0][tid] = s.pm[0][tid] + mv(s.K, s.innov, tid);
    __syncthreads();

    // thread-0 setup scalars
    double set_acc = 0.0, K0d = 0.0, ldfc0 = 0.0, LDSqd = 0.0, LDRqd = 0.0;
    if (tid == 0) {
        set_acc = -0.5 * (16.0 * LOG2PI + (double)LDpr)
                - 0.5 * (16.0 * LOG2PI + (double)LDe);
        K0d = -8.0 * LOG2PI - 0.5 * (double)LDe - 0.5 * (double)LDp + 8.0;
        ldfc0 = (double)ldqp + (double)LDRq - (double)ldS0;  // logdet(fc_0)
        LDSqd = (double)LDSq;
        LDRqd = (double)LDRq;
    }

    double accel = 0.0, d0 = 0.0;
    float lastld = 0.f;

    // ================= split pipeline =================
    if (tid < 128) {
        // -------- group A: Kalman recursion (fused stages) --------
        const int l = tid;
        const int ia0 = l >> 4, ia1 = ia0 + 8, ja = l & 15;
        const int e0 = ia0 * 16 + ja, e1 = ia1 * 16 + ja;
        float wqi0[16], wqi1[16], whi0[16], whi1[16], wqj[16], whj[16];
#pragma unroll
        for (int k = 0; k < 16; k++) {
            wqi0[k] = s.Wq[ia0 * 16 + k];
            wqi1[k] = s.Wq[ia1 * 16 + k];
            whi0[k] = s.WH[ia0 * 16 + k];
            whi1[k] = s.WH[ia1 * 16 + k];
            wqj[k] = s.Wq[ja * 16 + k];
            whj[k] = s.WH[ja * 16 + k];
        }
        for (int t = 1; t < Tn; t++) {
            const int w = t & 1, r = w ^ 1;
            // A1: M = Wq fc; U = WH fc; pm
            s.M[w][e0] = dot_rowreg_col(wqi0, s.fcb[r], ja);
            s.M[w][e1] = dot_rowreg_col(wqi1, s.fcb[r], ja);
            s.U[e0] = dot_rowreg_col(whi0, s.fcb[r], ja);
            s.U[e1] = dot_rowreg_col(whi1, s.fcb[r], ja);
            if (l < 16) {
                s.pm[w][l] = mv(s.Wq, s.fmb[r], l) + s.bq[l];
                s.y[l] = obs[t * 16 + l];
            }
            BARA();
            // A2: pc = M Wq^T + Sq; S = U WH^T + C2; Hpc = U Wq^T + C1; innov
            {
                float u0[16], u1[16], m0[16], m1[16];
#pragma unroll
                for (int k = 0; k < 16; k++) {
                    u0[k] = s.U[ia0 * 16 + k];
                    u1[k] = s.U[ia1 * 16 + k];
                    m0[k] = s.M[w][ia0 * 16 + k];
                    m1[k] = s.M[w][ia1 * 16 + k];
                }
                s.pc[w][e0] = dot_rr(m0, wqj) + s.Sq[e0];
                s.pc[w][e1] = dot_rr(m1, wqj) + s.Sq[e1];
                s.S[e0] = dot_rr(u0, whj) + s.C2[e0];
                s.S[e1] = dot_rr(u1, whj) + s.C2[e1];
                s.Hpc[e0] = dot_rr(u0, wqj) + s.C1[e0];
                s.Hpc[e1] = dot_rr(u1, wqj) + s.C1[e1];
            }
            if (l < 16) s.innov[l] = s.y[l] - mv(s.Hq, s.pm[w], l) - s.dq[l];
            BAR0();  // publish pc, M, pm to group B
            // A3: GJ(S, Hpc) -> K on warp 0
            if (wid == 0) {
                float ld = warp_gj_solve(s.S, s.Hpc, s.K, lane);
                d0 += (double)ld;  // sum lds
                lastld = ld;       // lds_N
            }
            BARA();
            // A4: fc' = pc - K Hpc; fm' = pm + K innov
            s.fcb[w][e0] = s.pc[w][e0] - dot_rc(s.K, s.Hpc, ia0, ja);
            s.fcb[w][e1] = s.pc[w][e1] - dot_rc(s.K, s.Hpc, ia1, ja);
            if (l < 16) s.fmb[w][l] = s.pm[w][l] + mv(s.K, s.innov, l);
            BARA();
        }
    } else {
        // -------- group B: side chain --------
        const int l = tid - 128;
        const int ib0 = l >> 4, ib1 = ib0 + 8, jb = l & 15;
        const int e0 = ib0 * 16 + jb, e1 = ib1 * 16 + jb;
        float wpi0[16], wpi1[16];
#pragma unroll
        for (int k = 0; k < 16; k++) {
            wpi0[k] = s.Wp[ib0 * 16 + k];
            wpi1[k] = s.Wp[ib1 * 16 + k];
        }
        for (int t = 1; t < Tn; t++) {
            const int w = t & 1, r = w ^ 1;
            BAR0();  // wait for pc, M, pm of step t
            // B1: GJ(pc, M) -> bA on warp 5
            if (wid == 5) {
                float ld = warp_gj_solve(s.pc[w], s.M[w], s.bA, lane);
                d0 += (double)ld;  // sum ldp
                lastld = ld;       // ldp_N
            }
            BARB();
            // B2: t1 = Wp bA - I; t2 = G bA; t3 = Go bA; stores
            s.t1[e0] = dot_rowreg_col(wpi0, s.bA, jb) - ((ib0 == jb) ? 1.f : 0.f);
            s.t1[e1] = dot_rowreg_col(wpi1, s.bA, jb) - ((ib1 == jb) ? 1.f : 0.f);
            s.t2[e0] = dot_rc(s.G, s.bA, ib0, jb);
            s.t2[e1] = dot_rc(s.G, s.bA, ib1, jb);
            s.t3[e0] = dot_rc(s.Go, s.bA, ib0, jb);
            s.t3[e1] = dot_rc(s.Go, s.bA, ib1, jb);
            g_P[t][e0] = s.bA[e0];
            g_P[t][e1] = s.bA[e1];
            if (l < 16) g_ba[t][l] = s.fmb[r][l] - mv(s.bA, s.pm[w], l);
            BARB();
            // B3: OmpA = Om_p t1; bcov elementwise; accumulate
            s.OmpA[e0] = dot_rc(s.Om_p, s.t1, ib0, jb);
            s.OmpA[e1] = dot_rc(s.Om_p, s.t1, ib1, jb);
            {
                float bc0 = s.fcb[r][e0] - dot_rc(s.bA, s.M[w], ib0, jb);
                float bc1 = s.fcb[r][e1] - dot_rc(s.bA, s.M[w], ib1, jb);
                accel += (double)((s.G[e0] + s.Go[e0] - 0.5f * s.Fm[e0]) * bc0)
                       + (double)((s.G[e1] + s.Go[e1] - 0.5f * s.Fm[e1]) * bc1);
            }
            BARB();
            // B4: G' = bA^T t2 + t1^T OmpA; Go' = bA^T t3 + Em
            {
                float g0 = dot_tc(s.bA, s.t2, ib0, jb) + dot_tc(s.t1, s.OmpA, ib0, jb);
                float g1 = dot_tc(s.bA, s.t2, ib1, jb) + dot_tc(s.t1, s.OmpA, ib1, jb);
                float go0 = dot_tc(s.bA, s.t3, ib0, jb) + s.Em[e0];
                float go1 = dot_tc(s.bA, s.t3, ib1, jb) + s.Em[e1];
                s.G[e0] = g0;
                s.G[e1] = g1;
                s.Go[e0] = go0;
                s.Go[e1] = go1;
            }
            BARB();
        }
    }
    __syncthreads();

    // ---- epilogue: publish constants + final state + partial sums ----
    g_OmP[tid] = s.Om_p[tid];
    g_om[tid] = s.om[tid];
    g_Om0[tid] = s.Om0[tid];
    {
        int fp = (Tn - 1) & 1;
        g_fcF[tid] = s.fcb[fp][tid];
        if (tid < 16) g_fmF[tid] = s.fmb[fp][tid];
    }
    double v = accel;
#pragma unroll
    for (int o = 16; o; o >>= 1) v += __shfl_xor_sync(0xffffffffu, v, o);
    if (lane == 0) s.dred[wid] = v;
    if (tid == 160) {
        s.dsc[0] = d0;               // SP = sum ldp_t
        s.dsc[1] = (double)lastld;   // ldp_N
    }
    __syncthreads();
    if (tid == 0) {
        double elem = 0.0;
#pragma unroll
        for (int w = 0; w < 8; w++) elem += s.dred[w];
        double SP = s.dsc[0], ldpN = s.dsc[1];
        double sumS = d0, ldsN = (double)lastld;
        double N = (double)(Tn - 1);
        double sumF = ldfc0 + (SP - ldpN) + (N - 1.0) * LDRqd - (sumS - ldsN);
        double FN = ldpN + LDRqd - ldsN;
        double sc = set_acc
                  + N * (K0d + 0.5 * LDSqd)
                  - 0.5 * SP
                  + 0.5 * sumF
                  + 0.5 * (16.0 * LOG2PI + FN) + 8.0
                  + elem;
        g_part[64] = sc;
    }
}

// ---------------- backward scan kernels ----------------
#define SEG 8
__global__ void __launch_bounds__(256, 1) lgq_scan1(int Tn) {
    const int b = blockIdx.x;
    const int lo = b * SEG;
    int hi = lo + SEG;
    if (hi > Tn) hi = Tn;
    __shared__ float R[256], Rn[256], bA[256];
    __shared__ float u[16], un[16], ba[16];
    const int tid = threadIdx.x;
    const int i = tid >> 4, j = tid & 15;
    R[tid] = (i == j) ? 1.f : 0.f;
    if (tid < 16) u[tid] = 0.f;
    __syncthreads();
    for (int t = hi - 1; t >= lo; t--) {
        g_Lr[t][tid] = R[tid];
        if (tid < 16) g_Lu[t][tid] = u[tid];
        if (t == 0) break;
        bA[tid] = g_P[t][tid];
        if (tid < 16) ba[tid] = g_ba[t][tid];
        __syncthreads();
        Rn[tid] = dot_rc(bA, R, i, j);
        if (tid < 16) un[tid] = ba[tid] + mv(bA, u, tid);
        __syncthreads();
        R[tid] = Rn[tid];
        if (tid < 16) u[tid] = un[tid];
        __syncthreads();
    }
    g_Sr[b][tid] = R[tid];
    if (tid < 16) g_Su[b][tid] = u[tid];
}

__global__ void __launch_bounds__(256, 1) lgq_scan2(int Tn) {
    const int nseg = (Tn + SEG - 1) / SEG;
    __shared__ float Gr[256], Gn[256], Sr[256];
    __shared__ float Gu[16], gn[16], Su[16];
    const int tid = threadIdx.x;
    const int i = tid >> 4, j = tid & 15;
    Gr[tid] = (i == j) ? 1.f : 0.f;
    if (tid < 16) Gu[tid] = 0.f;
    __syncthreads();
    for (int b = nseg - 1; b >= 0; b--) {
        g_Gr[b][tid] = Gr[tid];
        if (tid < 16) g_Gu[b][tid] = Gu[tid];
        if (b == 0) break;
        Sr[tid] = g_Sr[b][tid];
        if (tid < 16) Su[tid] = g_Su[b][tid];
        __syncthreads();
        Gn[tid] = dot_rc(Sr, Gr, i, j);
        if (tid < 16) gn[tid] = mv(Sr, Gu, tid) + Su[tid];
        __syncthreads();
        Gr[tid] = Gn[tid];
        if (tid < 16) Gu[tid] = gn[tid];
        __syncthreads();
    }
}

#define EVT 4
__global__ void __launch_bounds__(256, 1) lgq_scan3(
    const float* obs, const float* p_trans_w, const float* p_trans_b,
    const float* p_emis_w, const float* p_emis_b, const float* p_prior_mean,
    int Tn) {
    const int b = blockIdx.x;
    const int lo = b * EVT;
    int hi = lo + EVT;
    if (hi > Tn) hi = Tn;
    const int seg = lo / SEG;
    __shared__ float OmP[256], omm[256], Om0[256], Wp[256], Wep[256], fc[256], Gr[256];
    __shared__ float Lr[256], bA[256], Rf[256], Ai[256], A[256], Ao[256], AF[256], AoF[256];
    __shared__ float fm[16], Gu[16], Lu[16], bav[16], uf[16], Bv[16], Bo[16];
    __shared__ float cv[16], co[16], y[16], bp[16], ebp[16], ppm[16];
    __shared__ double dred[8];
    const int tid = threadIdx.x;
    const int i = tid >> 4, j = tid & 15;
    const int lane = tid & 31, wid = tid >> 5;

    OmP[tid] = g_OmP[tid];
    omm[tid] = g_om[tid];
    Om0[tid] = g_Om0[tid];
    Wp[tid] = p_trans_w[tid];
    Wep[tid] = p_emis_w[tid];
    fc[tid] = g_fcF[tid];
    Gr[tid] = g_Gr[seg][tid];
    if (tid < 16) {
        fm[tid] = g_fmF[tid];
        Gu[tid] = g_Gu[seg][tid];
        bp[tid] = p_trans_b[tid];
        ebp[tid] = p_emis_b[tid];
        ppm[tid] = p_prior_mean[tid];
    }
    __syncthreads();

    double acc = 0.0;
    for (int t = lo; t < hi; t++) {
        // st0: stage loads
        Lr[tid] = g_Lr[t][tid];
        bA[tid] = (t > 0) ? g_P[t][tid] : 0.f;
        if (tid < 16) {
            Lu[tid] = g_Lu[t][tid];
            bav[tid] = (t > 0) ? g_ba[t][tid] : 0.f;
            y[tid] = obs[t * 16 + tid];
        }
        __syncthreads();
        // st1: Rf = Lr Gr; Ai; uf; Bv init
        Rf[tid] = dot_rc(Lr, Gr, i, j);
        Ai[tid] = (t > 0) ? (dot_rc(Wp, bA, i, j) - ((i == j) ? 1.f : 0.f))
                          : ((i == j) ? 1.f : 0.f);
        if (tid < 16) {
            uf[tid] = mv(Lr, Gu, tid) + Lu[tid];
            Bv[tid] = (t > 0) ? (mv(Wp, bav, tid) + bp[tid]) : (-ppm[tid]);
        }
        __syncthreads();
        // st2: A = Ai Rf; Ao = Wep Rf; B vectors
        A[tid] = dot_rc(Ai, Rf, i, j);
        Ao[tid] = dot_rc(Wep, Rf, i, j);
        if (tid < 16) {
            Bv[tid] += mv(Ai, uf, tid);
            Bo[tid] = ebp[tid] - y[tid] + mv(Wep, uf, tid);
        }
        __syncthreads();
        // st3: AF = A fc; AoF = Ao fc; cv, co
        AF[tid] = dot_rc(A, fc, i, j);
        AoF[tid] = dot_rc(Ao, fc, i, j);
        if (tid < 16) {
            cv[tid] = mv(A, fm, tid) + Bv[tid];
            co[tid] = mv(Ao, fm, tid) + Bo[tid];
        }
        __syncthreads();
        // st4: accumulate
        {
            const float* Om = (t == 0) ? Om0 : OmP;
            float val = Om[tid] * (dot_rc(AF, A, i, j) + cv[i] * cv[j])
                      + omm[tid] * (dot_rc(AoF, Ao, i, j) + co[i] * co[j]);
            acc += (double)val;
        }
        __syncthreads();
    }

    double v = acc;
#pragma unroll
    for (int o = 16; o; o >>= 1) v += __shfl_xor_sync(0xffffffffu, v, o);
    if (lane == 0) dred[wid] = v;
    __syncthreads();
    if (tid == 0) {
        double tot = 0.0;
#pragma unroll
        for (int w = 0; w < 8; w++) tot += dred[w];
        g_part[b] = tot;
    }
}

__global__ void lgq_fin(float* out, int Tn) {
    if (threadIdx.x == 0) {
        const int nblk = (Tn + EVT - 1) / EVT;
        double tot = g_part[64];
        for (int b = 0; b < nblk; b++) tot += g_part[b];
        out[0] = (float)tot;
    }
}

extern "C" void kernel_launch(void* const* d_in, const int* in_sizes, int n_in,
                              void* d_out, int out_size) {
    int Tn = in_sizes[0] / 16;
    if (Tn > TMAX) Tn = TMAX;
    const int nseg = (Tn + SEG - 1) / SEG;
    const int nblk = (Tn + EVT - 1) / EVT;
    lgq_fwd<<<1, 256>>>(
        (const float*)d_in[0], (const float*)d_in[1], (const float*)d_in[2],
        (const float*)d_in[3], (const float*)d_in[4], (const float*)d_in[5],
        (const float*)d_in[6], (const float*)d_in[7], (const float*)d_in[8],
        (const float*)d_in[9], (const float*)d_in[10], (const float*)d_in[11],
        (const float*)d_in[12], (const float*)d_in[13], (const float*)d_in[14],
        (const float*)d_in[15], (const float*)d_in[16], Tn);
    lgq_scan1<<<nseg, 256>>>(Tn);
    lgq_scan2<<<1, 256>>>(Tn);
    lgq_scan3<<<nblk, 256>>>(
        (const float*)d_in[0], (const float*)d_in[3], (const float*)d_in[4],
        (const float*)d_in[6], (const float*)d_in[7], (const float*)d_in[1], Tn);
    lgq_fin<<<1, 32>>>((float*)d_out, Tn);
}